// round 7
// baseline (speedup 1.0000x reference)
#include <cuda_runtime.h>
#include <cuda_fp16.h>
#include <cstdint>

// Problem dims (fixed by the dataset)
constexpr int B  = 8;
constexpr int TQ = 2048;
constexpr int TK = 2048;
constexpr int D  = 1024;
constexpr float NEG_INF = -1e9f;

constexpr int KC = 32;                    // K floats per chunk
constexpr int QK_CHUNKS = D  / KC;        // 32
constexpr int PV_CHUNKS = TK / KC;        // 64

// smem pitches (in halfs)
constexpr int PA = 40;                    // 32 used + 8 pad (conflict-free ldmatrix)
constexpr int PB = 136;                   // PV V-tile: 128 used + 8 pad

constexpr int QK_TILE  = 128 * PA * 2;            // 10240 B
constexpr int QK_STAGE = 4 * QK_TILE;             // Ah, Al, Bh, Bl
constexpr int QK_MASK  = 2 * QK_STAGE;
constexpr int QK_SMEM  = QK_MASK + 512;

constexpr int PV_ATILE = 128 * PA * 2;
constexpr int PV_BTILE = 32 * PB * 2;
constexpr int PV_STAGE = 2 * PV_ATILE + 2 * PV_BTILE;
constexpr int PV_SMEM  = 2 * PV_STAGE;

constexpr int NT = 512;                   // threads per CTA (16 warps, 4x4 grid)

// ---------------------------------------------------------------- helpers
__device__ __forceinline__ uint32_t smem_u32(const void* p) {
    return (uint32_t)__cvta_generic_to_shared(p);
}
__device__ __forceinline__ void ldsm4(uint32_t r[4], uint32_t addr) {
    asm volatile("ldmatrix.sync.aligned.m8n8.x4.shared.b16 {%0,%1,%2,%3}, [%4];"
                 : "=r"(r[0]), "=r"(r[1]), "=r"(r[2]), "=r"(r[3]) : "r"(addr));
}
__device__ __forceinline__ void ldsm4t(uint32_t r[4], uint32_t addr) {
    asm volatile("ldmatrix.sync.aligned.m8n8.x4.trans.shared.b16 {%0,%1,%2,%3}, [%4];"
                 : "=r"(r[0]), "=r"(r[1]), "=r"(r[2]), "=r"(r[3]) : "r"(addr));
}
__device__ __forceinline__ void mma16816(float c[4], const uint32_t a[4],
                                         uint32_t b0, uint32_t b1) {
    asm volatile(
        "mma.sync.aligned.m16n8k16.row.col.f32.f16.f16.f32 "
        "{%0,%1,%2,%3},{%4,%5,%6,%7},{%8,%9},{%0,%1,%2,%3};\n"
        : "+f"(c[0]), "+f"(c[1]), "+f"(c[2]), "+f"(c[3])
        : "r"(a[0]), "r"(a[1]), "r"(a[2]), "r"(a[3]), "r"(b0), "r"(b1));
}
__device__ __forceinline__ void split4(float4 v, uint2& hi, uint2& lo) {
    __half2 h0 = __float22half2_rn(make_float2(v.x, v.y));
    __half2 h1 = __float22half2_rn(make_float2(v.z, v.w));
    float2 f0 = __half22float2(h0), f1 = __half22float2(h1);
    __half2 l0 = __float22half2_rn(make_float2(v.x - f0.x, v.y - f0.y));
    __half2 l1 = __float22half2_rn(make_float2(v.z - f1.x, v.w - f1.y));
    hi = make_uint2(*(uint32_t*)&h0, *(uint32_t*)&h1);
    lo = make_uint2(*(uint32_t*)&l0, *(uint32_t*)&l1);
}

// ------------------------------------------------------------ QK^T + mask (fp16 3-term)
// Block tile 128(M) x 128(N) x 32(K). 16 warps 4x4, warp tile 32x32.
__global__ __launch_bounds__(NT, 1) void qk_kernel(
    const float* __restrict__ dec, const float* __restrict__ enc,
    const int* __restrict__ mask, float* __restrict__ S)
{
    extern __shared__ char smem[];
    const int tid = threadIdx.x, warp = tid >> 5, lane = tid & 31;
    const int g = lane >> 2, tg = lane & 3;
    const int r8 = lane & 7, sub = lane >> 3;
    const int wm = warp >> 2, wn = warp & 3;   // 4 x 4 warp grid
    const int bz = blockIdx.z, bm = blockIdx.y, bn = blockIdx.x;

    if (tid < 128) ((int*)(smem + QK_MASK))[tid] = mask[bz * TK + bn * 128 + tid];

    const float* Ag = dec + ((size_t)bz * TQ + bm * 128) * D;
    const float* Bg = enc + ((size_t)bz * TK + bn * 128) * D;

    float acc[2][4][4];
#pragma unroll
    for (int i = 0; i < 2; i++)
#pragma unroll
        for (int j = 0; j < 4; j++)
#pragma unroll
            for (int t = 0; t < 4; t++) acc[i][j][t] = 0.f;

    const uint32_t sb = smem_u32(smem);

    float4 ra[2], rb[2];
    // prologue: chunk0 -> regs -> buf0 ; chunk1 -> regs
#pragma unroll
    for (int i = 0; i < 2; i++) {
        int p = tid + NT * i, r = p >> 3, qq = p & 7;
        ra[i] = *(const float4*)(Ag + (size_t)r * D + qq * 4);
        rb[i] = *(const float4*)(Bg + (size_t)r * D + qq * 4);
    }
    {
        char* Ah = smem;                 char* Al = Ah + QK_TILE;
        char* Bh = Al + QK_TILE;         char* Bl = Bh + QK_TILE;
#pragma unroll
        for (int i = 0; i < 2; i++) {
            int p = tid + NT * i, r = p >> 3, qq = p & 7;
            uint32_t off = r * (PA * 2) + qq * 8;
            uint2 hi, lo;
            split4(ra[i], hi, lo);
            *(uint2*)(Ah + off) = hi;  *(uint2*)(Al + off) = lo;
            split4(rb[i], hi, lo);
            *(uint2*)(Bh + off) = hi;  *(uint2*)(Bl + off) = lo;
        }
#pragma unroll
        for (int i = 0; i < 2; i++) {
            int p = tid + NT * i, r = p >> 3, qq = p & 7;
            ra[i] = *(const float4*)(Ag + (size_t)r * D + KC + qq * 4);
            rb[i] = *(const float4*)(Bg + (size_t)r * D + KC + qq * 4);
        }
    }
    __syncthreads();

    for (int k = 0; k < QK_CHUNKS; k++) {
        const int buf = k & 1;
        const uint32_t sAh = sb + buf * QK_STAGE;
        const uint32_t sAl = sAh + QK_TILE;
        const uint32_t sBh = sAl + QK_TILE;
        const uint32_t sBl = sBh + QK_TILE;
        char* nAh = smem + (buf ^ 1) * QK_STAGE;
        char* nAl = nAh + QK_TILE;
        char* nBh = nAl + QK_TILE;
        char* nBl = nBh + QK_TILE;

        const uint32_t aoff = (wm * 32 + r8 + (sub & 1) * 8) * (PA * 2) + ((sub >> 1) * 8) * 2;
        const uint32_t boff = (wn * 32 + r8 + (sub >> 1) * 8) * (PA * 2) + ((sub & 1) * 8) * 2;

        uint32_t fah[2][4], fal[2][4], fbh[2][4], fbl[2][4];

#pragma unroll
        for (int kk = 0; kk < 2; kk++) {
            const uint32_t ko16 = kk * 32;   // 16 halfs = 32 bytes
#pragma unroll
            for (int i = 0; i < 2; i++) {
                ldsm4(fah[i], sAh + aoff + ko16 + i * 16 * (PA * 2));
                ldsm4(fal[i], sAl + aoff + ko16 + i * 16 * (PA * 2));
            }
#pragma unroll
            for (int jp = 0; jp < 2; jp++) {
                ldsm4(fbh[jp], sBh + boff + ko16 + jp * 16 * (PA * 2));
                ldsm4(fbl[jp], sBl + boff + ko16 + jp * 16 * (PA * 2));
            }
            if (kk == 0) {
                // overlap: split + store chunk k+1 into the other buffer
                if (k + 1 < QK_CHUNKS) {
#pragma unroll
                    for (int i = 0; i < 2; i++) {
                        int p = tid + NT * i, r = p >> 3, qq = p & 7;
                        uint32_t off = r * (PA * 2) + qq * 8;
                        uint2 hi, lo;
                        split4(ra[i], hi, lo);
                        *(uint2*)(nAh + off) = hi;  *(uint2*)(nAl + off) = lo;
                        split4(rb[i], hi, lo);
                        *(uint2*)(nBh + off) = hi;  *(uint2*)(nBl + off) = lo;
                    }
                }
            } else {
                // overlap: prefetch chunk k+2 into regs
                if (k + 2 < QK_CHUNKS) {
                    const int ko = (k + 2) * KC;
#pragma unroll
                    for (int i = 0; i < 2; i++) {
                        int p = tid + NT * i, r = p >> 3, qq = p & 7;
                        ra[i] = *(const float4*)(Ag + (size_t)r * D + ko + qq * 4);
                        rb[i] = *(const float4*)(Bg + (size_t)r * D + ko + qq * 4);
                    }
                }
            }
#pragma unroll
            for (int i = 0; i < 2; i++)
#pragma unroll
                for (int j = 0; j < 4; j++) {
                    int jp = j >> 1, o = (j & 1) * 2;
                    mma16816(acc[i][j], fah[i], fbh[jp][o], fbh[jp][o + 1]);
                    mma16816(acc[i][j], fah[i], fbl[jp][o], fbl[jp][o + 1]);
                    mma16816(acc[i][j], fal[i], fbh[jp][o], fbh[jp][o + 1]);
                }
        }
        __syncthreads();
    }

    // epilogue: add mask, store masked logits
    const int* ms = (const int*)(smem + QK_MASK);
#pragma unroll
    for (int j = 0; j < 4; j++) {
        int c0 = wn * 32 + j * 8 + 2 * tg;
        float t0 = (1.0f - (float)ms[c0]) * NEG_INF;
        float t1 = (1.0f - (float)ms[c0 + 1]) * NEG_INF;
#pragma unroll
        for (int i = 0; i < 2; i++) {
            int r0 = bm * 128 + wm * 32 + i * 16 + g;
            size_t base = ((size_t)bz * TQ + r0) * TK + bn * 128 + c0;
            *(float2*)(&S[base]) = make_float2(acc[i][j][0] + t0, acc[i][j][1] + t1);
            *(float2*)(&S[base + (size_t)8 * TK]) = make_float2(acc[i][j][2] + t0, acc[i][j][3] + t1);
        }
    }
}

// ------------------------------------------------------------ row softmax (in place)
__global__ __launch_bounds__(256) void softmax_kernel(float* __restrict__ W)
{
    const size_t row = blockIdx.x;
    float4* p = reinterpret_cast<float4*>(W + row * TK);
    const int tid = threadIdx.x;
    const int lane = tid & 31, warp = tid >> 5;
    __shared__ float red[8];

    float4 v0 = p[tid];
    float4 v1 = p[tid + 256];

    float mx = fmaxf(fmaxf(fmaxf(v0.x, v0.y), fmaxf(v0.z, v0.w)),
                     fmaxf(fmaxf(v1.x, v1.y), fmaxf(v1.z, v1.w)));
#pragma unroll
    for (int o = 16; o; o >>= 1) mx = fmaxf(mx, __shfl_xor_sync(0xffffffffu, mx, o));
    if (lane == 0) red[warp] = mx;
    __syncthreads();
    float bmax = red[0];
#pragma unroll
    for (int i = 1; i < 8; i++) bmax = fmaxf(bmax, red[i]);
    __syncthreads();

    v0.x = __expf(v0.x - bmax); v0.y = __expf(v0.y - bmax);
    v0.z = __expf(v0.z - bmax); v0.w = __expf(v0.w - bmax);
    v1.x = __expf(v1.x - bmax); v1.y = __expf(v1.y - bmax);
    v1.z = __expf(v1.z - bmax); v1.w = __expf(v1.w - bmax);

    float s = (v0.x + v0.y + v0.z + v0.w) + (v1.x + v1.y + v1.z + v1.w);
#pragma unroll
    for (int o = 16; o; o >>= 1) s += __shfl_xor_sync(0xffffffffu, s, o);
    if (lane == 0) red[warp] = s;
    __syncthreads();
    float bsum = red[0];
#pragma unroll
    for (int i = 1; i < 8; i++) bsum += red[i];

    const float inv = 1.0f / bsum;
    v0.x *= inv; v0.y *= inv; v0.z *= inv; v0.w *= inv;
    v1.x *= inv; v1.y *= inv; v1.z *= inv; v1.w *= inv;
    p[tid] = v0;
    p[tid + 256] = v1;
}

// ------------------------------------------------------------ P @ V (fp16 3-term)
// A = W (K-major, ldmatrix). V chunk stored [k][d], read via ldmatrix.trans.
__global__ __launch_bounds__(NT, 1) void pv_kernel(
    const float* __restrict__ W, const float* __restrict__ enc, float* __restrict__ ctx)
{
    extern __shared__ char smem[];
    const int tid = threadIdx.x, warp = tid >> 5, lane = tid & 31;
    const int g = lane >> 2, tg = lane & 3;
    const int r8 = lane & 7, sub = lane >> 3;
    const int wm = warp >> 2, wn = warp & 3;
    const int bz = blockIdx.z, bm = blockIdx.y, bn = blockIdx.x;

    const float* Ag = W + ((size_t)bz * TQ + bm * 128) * TK;
    const float* Eg = enc + (size_t)bz * TK * D + bn * 128;

    float acc[2][4][4];
#pragma unroll
    for (int i = 0; i < 2; i++)
#pragma unroll
        for (int j = 0; j < 4; j++)
#pragma unroll
            for (int t = 0; t < 4; t++) acc[i][j][t] = 0.f;

    const uint32_t sb = smem_u32(smem);

    float4 ra[2], rv[2];
#pragma unroll
    for (int i = 0; i < 2; i++) {
        int p = tid + NT * i, r = p >> 3, qq = p & 7;
        ra[i] = *(const float4*)(Ag + (size_t)r * TK + qq * 4);
        int krow = p >> 5, dq = p & 31;
        rv[i] = *(const float4*)(Eg + (size_t)krow * D + dq * 4);
    }
    {
        char* Ah = smem;                 char* Al = Ah + PV_ATILE;
        char* Vh = Al + PV_ATILE;        char* Vl = Vh + PV_BTILE;
#pragma unroll
        for (int i = 0; i < 2; i++) {
            int p = tid + NT * i, r = p >> 3, qq = p & 7;
            uint32_t off = r * (PA * 2) + qq * 8;
            uint2 hi, lo;
            split4(ra[i], hi, lo);
            *(uint2*)(Ah + off) = hi;  *(uint2*)(Al + off) = lo;
            int krow = p >> 5, dq = p & 31;
            uint32_t voff = krow * (PB * 2) + dq * 8;
            split4(rv[i], hi, lo);
            *(uint2*)(Vh + voff) = hi; *(uint2*)(Vl + voff) = lo;
        }
#pragma unroll
        for (int i = 0; i < 2; i++) {
            int p = tid + NT * i, r = p >> 3, qq = p & 7;
            ra[i] = *(const float4*)(Ag + (size_t)r * TK + KC + qq * 4);
            int krow = p >> 5, dq = p & 31;
            rv[i] = *(const float4*)(Eg + (size_t)(KC + krow) * D + dq * 4);
        }
    }
    __syncthreads();

    for (int k = 0; k < PV_CHUNKS; k++) {
        const int buf = k & 1;
        const uint32_t sAh = sb + buf * PV_STAGE;
        const uint32_t sAl = sAh + PV_ATILE;
        const uint32_t sVh = sAl + PV_ATILE;
        const uint32_t sVl = sVh + PV_BTILE;
        char* nAh = smem + (buf ^ 1) * PV_STAGE;
        char* nAl = nAh + PV_ATILE;
        char* nVh = nAl + PV_ATILE;
        char* nVl = nVh + PV_BTILE;

        const uint32_t aoff = (wm * 32 + r8 + (sub & 1) * 8) * (PA * 2) + ((sub >> 1) * 8) * 2;
        const uint32_t voff = (r8 + (sub & 1) * 8) * (PB * 2)
                            + (wn * 32 + (sub >> 1) * 8) * 2;

        uint32_t fah[2][4], fal[2][4], fbh[2][4], fbl[2][4];

#pragma unroll
        for (int kk = 0; kk < 2; kk++) {
#pragma unroll
            for (int i = 0; i < 2; i++) {
                ldsm4(fah[i], sAh + aoff + kk * 32 + i * 16 * (PA * 2));
                ldsm4(fal[i], sAl + aoff + kk * 32 + i * 16 * (PA * 2));
            }
#pragma unroll
            for (int jp = 0; jp < 2; jp++) {
                ldsm4t(fbh[jp], sVh + voff + kk * 16 * (PB * 2) + jp * 16 * 2);
                ldsm4t(fbl[jp], sVl + voff + kk * 16 * (PB * 2) + jp * 16 * 2);
            }
            if (kk == 0) {
                if (k + 1 < PV_CHUNKS) {
#pragma unroll
                    for (int i = 0; i < 2; i++) {
                        int p = tid + NT * i, r = p >> 3, qq = p & 7;
                        uint32_t off = r * (PA * 2) + qq * 8;
                        uint2 hi, lo;
                        split4(ra[i], hi, lo);
                        *(uint2*)(nAh + off) = hi;  *(uint2*)(nAl + off) = lo;
                        int krow = p >> 5, dq = p & 31;
                        uint32_t voff2 = krow * (PB * 2) + dq * 8;
                        split4(rv[i], hi, lo);
                        *(uint2*)(nVh + voff2) = hi; *(uint2*)(nVl + voff2) = lo;
                    }
                }
            } else {
                if (k + 2 < PV_CHUNKS) {
                    const int ko = (k + 2) * KC;
#pragma unroll
                    for (int i = 0; i < 2; i++) {
                        int p = tid + NT * i, r = p >> 3, qq = p & 7;
                        ra[i] = *(const float4*)(Ag + (size_t)r * TK + ko + qq * 4);
                        int krow = p >> 5, dq = p & 31;
                        rv[i] = *(const float4*)(Eg + (size_t)(ko + krow) * D + dq * 4);
                    }
                }
            }
#pragma unroll
            for (int i = 0; i < 2; i++)
#pragma unroll
                for (int j = 0; j < 4; j++) {
                    int jp = j >> 1, o = (j & 1) * 2;
                    mma16816(acc[i][j], fah[i], fbh[jp][o], fbh[jp][o + 1]);
                    mma16816(acc[i][j], fah[i], fbl[jp][o], fbl[jp][o + 1]);
                    mma16816(acc[i][j], fal[i], fbh[jp][o], fbh[jp][o + 1]);
                }
        }
        __syncthreads();
    }

#pragma unroll
    for (int j = 0; j < 4; j++) {
        int c0 = wn * 32 + j * 8 + 2 * tg;
#pragma unroll
        for (int i = 0; i < 2; i++) {
            int r0 = bm * 128 + wm * 32 + i * 16 + g;
            size_t base = ((size_t)bz * TQ + r0) * D + bn * 128 + c0;
            *(float2*)(&ctx[base]) = make_float2(acc[i][j][0], acc[i][j][1]);
            *(float2*)(&ctx[base + (size_t)8 * D]) = make_float2(acc[i][j][2], acc[i][j][3]);
        }
    }
}

// ---------------------------------------------------------------- launcher
extern "C" void kernel_launch(void* const* d_in, const int* in_sizes, int n_in,
                              void* d_out, int out_size)
{
    const float* dec  = (const float*)d_in[0];   // [B, TQ, D]
    const float* enc  = (const float*)d_in[1];   // [B, TK, D]
    const int*   mask = (const int*)d_in[2];     // [B, TK]
    float* out = (float*)d_out;

    float* ctx = out;                              // [B, TQ, D]
    float* Wgt = out + (size_t)B * TQ * D;         // [B, TQ, TK]

    cudaFuncSetAttribute(qk_kernel, cudaFuncAttributeMaxDynamicSharedMemorySize, QK_SMEM);
    cudaFuncSetAttribute(pv_kernel, cudaFuncAttributeMaxDynamicSharedMemorySize, PV_SMEM);

    dim3 g1(TK / 128, TQ / 128, B);
    qk_kernel<<<g1, NT, QK_SMEM>>>(dec, enc, mask, Wgt);

    softmax_kernel<<<B * TQ, 256>>>(Wgt);

    dim3 g3(D / 128, TQ / 128, B);
    pv_kernel<<<g3, NT, PV_SMEM>>>(Wgt, enc, ctx);
}

// round 8
// speedup vs baseline: 1.2325x; 1.2325x over previous
#include <cuda_runtime.h>
#include <cuda_fp16.h>
#include <cstdint>

// Problem dims (fixed by the dataset)
constexpr int B  = 8;
constexpr int TQ = 2048;
constexpr int TK = 2048;
constexpr int D  = 1024;
constexpr float NEG_INF = -1e9f;

constexpr int KC = 64;                    // K floats per chunk
constexpr int QK_CHUNKS = D  / KC;        // 16
constexpr int PV_CHUNKS = TK / KC;        // 32

// smem pitches (in halfs)
constexpr int PA = 72;                    // 64 used + 8 pad (conflict-free ldmatrix)
constexpr int PB = 136;                   // PV V-tile: 128 used + 8 pad

constexpr int QK_TILE  = 128 * PA * 2;            // 18432 B
constexpr int QK_STAGE = 4 * QK_TILE;             // Ah, Al, Bh, Bl = 73728
constexpr int QK_MASK  = 2 * QK_STAGE;            // 147456
constexpr int QK_SMEM  = QK_MASK + 512;

constexpr int PV_ATILE = 128 * PA * 2;            // 18432
constexpr int PV_VTILE = 64 * PB * 2;             // 17408 (Vh only — 2-term)
constexpr int PV_STAGE = 2 * PV_ATILE + PV_VTILE; // 54272
constexpr int PV_SMEM  = 2 * PV_STAGE;            // 108544

constexpr int NT = 512;                   // 16 warps, 4x4 grid, warp tile 32x32

// ---------------------------------------------------------------- helpers
__device__ __forceinline__ uint32_t smem_u32(const void* p) {
    return (uint32_t)__cvta_generic_to_shared(p);
}
__device__ __forceinline__ void ldsm4(uint32_t r[4], uint32_t addr) {
    asm volatile("ldmatrix.sync.aligned.m8n8.x4.shared.b16 {%0,%1,%2,%3}, [%4];"
                 : "=r"(r[0]), "=r"(r[1]), "=r"(r[2]), "=r"(r[3]) : "r"(addr));
}
__device__ __forceinline__ void ldsm4t(uint32_t r[4], uint32_t addr) {
    asm volatile("ldmatrix.sync.aligned.m8n8.x4.trans.shared.b16 {%0,%1,%2,%3}, [%4];"
                 : "=r"(r[0]), "=r"(r[1]), "=r"(r[2]), "=r"(r[3]) : "r"(addr));
}
__device__ __forceinline__ void mma16816(float c[4], const uint32_t a[4],
                                         uint32_t b0, uint32_t b1) {
    asm volatile(
        "mma.sync.aligned.m16n8k16.row.col.f32.f16.f16.f32 "
        "{%0,%1,%2,%3},{%4,%5,%6,%7},{%8,%9},{%0,%1,%2,%3};\n"
        : "+f"(c[0]), "+f"(c[1]), "+f"(c[2]), "+f"(c[3])
        : "r"(a[0]), "r"(a[1]), "r"(a[2]), "r"(a[3]), "r"(b0), "r"(b1));
}
__device__ __forceinline__ void split4(float4 v, uint2& hi, uint2& lo) {
    __half2 h0 = __float22half2_rn(make_float2(v.x, v.y));
    __half2 h1 = __float22half2_rn(make_float2(v.z, v.w));
    float2 f0 = __half22float2(h0), f1 = __half22float2(h1);
    __half2 l0 = __float22half2_rn(make_float2(v.x - f0.x, v.y - f0.y));
    __half2 l1 = __float22half2_rn(make_float2(v.z - f1.x, v.w - f1.y));
    hi = make_uint2(*(uint32_t*)&h0, *(uint32_t*)&h1);
    lo = make_uint2(*(uint32_t*)&l0, *(uint32_t*)&l1);
}
__device__ __forceinline__ uint2 hi4(float4 v) {
    __half2 h0 = __float22half2_rn(make_float2(v.x, v.y));
    __half2 h1 = __float22half2_rn(make_float2(v.z, v.w));
    return make_uint2(*(uint32_t*)&h0, *(uint32_t*)&h1);
}

// ------------------------------------------------------------ QK^T + mask (fp16 3-term)
// Block tile 128(M) x 128(N) x 64(K). 16 warps 4x4, warp tile 32x32.
__global__ __launch_bounds__(NT, 1) void qk_kernel(
    const float* __restrict__ dec, const float* __restrict__ enc,
    const int* __restrict__ mask, float* __restrict__ S)
{
    extern __shared__ char smem[];
    const int tid = threadIdx.x, warp = tid >> 5, lane = tid & 31;
    const int g = lane >> 2, tg = lane & 3;
    const int r8 = lane & 7, sub = lane >> 3;
    const int wm = warp >> 2, wn = warp & 3;   // 4 x 4 warp grid
    const int bz = blockIdx.z, bm = blockIdx.y, bn = blockIdx.x;

    if (tid < 128) ((int*)(smem + QK_MASK))[tid] = mask[bz * TK + bn * 128 + tid];

    const float* Ag = dec + ((size_t)bz * TQ + bm * 128) * D;
    const float* Bg = enc + ((size_t)bz * TK + bn * 128) * D;

    float acc[2][4][4];
#pragma unroll
    for (int i = 0; i < 2; i++)
#pragma unroll
        for (int j = 0; j < 4; j++)
#pragma unroll
            for (int t = 0; t < 4; t++) acc[i][j][t] = 0.f;

    const uint32_t sb = smem_u32(smem);

    // per-thread load slots: p = tid + NT*i (i<4); row = p>>4 (16 float4/row), q = p&15
    float4 ra[4], rb[4];
#pragma unroll
    for (int i = 0; i < 4; i++) {
        int p = tid + NT * i, r = p >> 4, qq = p & 15;
        ra[i] = *(const float4*)(Ag + (size_t)r * D + qq * 4);
        rb[i] = *(const float4*)(Bg + (size_t)r * D + qq * 4);
    }
    {   // store chunk0 -> buf0; load chunk1 -> regs
        char* Ah = smem;                 char* Al = Ah + QK_TILE;
        char* Bh = Al + QK_TILE;         char* Bl = Bh + QK_TILE;
#pragma unroll
        for (int i = 0; i < 4; i++) {
            int p = tid + NT * i, r = p >> 4, qq = p & 15;
            uint32_t off = r * (PA * 2) + qq * 8;
            uint2 hi, lo;
            split4(ra[i], hi, lo);
            *(uint2*)(Ah + off) = hi;  *(uint2*)(Al + off) = lo;
            split4(rb[i], hi, lo);
            *(uint2*)(Bh + off) = hi;  *(uint2*)(Bl + off) = lo;
        }
#pragma unroll
        for (int i = 0; i < 4; i++) {
            int p = tid + NT * i, r = p >> 4, qq = p & 15;
            ra[i] = *(const float4*)(Ag + (size_t)r * D + KC + qq * 4);
            rb[i] = *(const float4*)(Bg + (size_t)r * D + KC + qq * 4);
        }
    }
    __syncthreads();

    for (int k = 0; k < QK_CHUNKS; k++) {
        const int buf = k & 1;
        const uint32_t sAh = sb + buf * QK_STAGE;
        const uint32_t sAl = sAh + QK_TILE;
        const uint32_t sBh = sAl + QK_TILE;
        const uint32_t sBl = sBh + QK_TILE;
        char* nAh = smem + (buf ^ 1) * QK_STAGE;
        char* nAl = nAh + QK_TILE;
        char* nBh = nAl + QK_TILE;
        char* nBl = nBh + QK_TILE;

        const uint32_t aoff = (wm * 32 + r8 + (sub & 1) * 8) * (PA * 2) + ((sub >> 1) * 8) * 2;
        const uint32_t boff = (wn * 32 + r8 + (sub >> 1) * 8) * (PA * 2) + ((sub & 1) * 8) * 2;

        uint32_t fah[2][4], fal[2][4], fbh[2][4], fbl[2][4];

#pragma unroll
        for (int kk = 0; kk < 4; kk++) {
            const uint32_t ko16 = kk * 32;   // 16 halfs = 32 bytes
#pragma unroll
            for (int i = 0; i < 2; i++) {
                ldsm4(fah[i], sAh + aoff + ko16 + i * 16 * (PA * 2));
                ldsm4(fal[i], sAl + aoff + ko16 + i * 16 * (PA * 2));
            }
#pragma unroll
            for (int jp = 0; jp < 2; jp++) {
                ldsm4(fbh[jp], sBh + boff + ko16 + jp * 16 * (PA * 2));
                ldsm4(fbl[jp], sBl + boff + ko16 + jp * 16 * (PA * 2));
            }
            if (kk == 0) {
                // overlap: split + store chunk k+1 into the other buffer
                if (k + 1 < QK_CHUNKS) {
#pragma unroll
                    for (int i = 0; i < 4; i++) {
                        int p = tid + NT * i, r = p >> 4, qq = p & 15;
                        uint32_t off = r * (PA * 2) + qq * 8;
                        uint2 hi, lo;
                        split4(ra[i], hi, lo);
                        *(uint2*)(nAh + off) = hi;  *(uint2*)(nAl + off) = lo;
                        split4(rb[i], hi, lo);
                        *(uint2*)(nBh + off) = hi;  *(uint2*)(nBl + off) = lo;
                    }
                }
            } else if (kk == 2) {
                // overlap: prefetch chunk k+2 into regs
                if (k + 2 < QK_CHUNKS) {
                    const int ko = (k + 2) * KC;
#pragma unroll
                    for (int i = 0; i < 4; i++) {
                        int p = tid + NT * i, r = p >> 4, qq = p & 15;
                        ra[i] = *(const float4*)(Ag + (size_t)r * D + ko + qq * 4);
                        rb[i] = *(const float4*)(Bg + (size_t)r * D + ko + qq * 4);
                    }
                }
            }
#pragma unroll
            for (int i = 0; i < 2; i++)
#pragma unroll
                for (int j = 0; j < 4; j++) {
                    int jp = j >> 1, o = (j & 1) * 2;
                    mma16816(acc[i][j], fah[i], fbh[jp][o], fbh[jp][o + 1]);
                    mma16816(acc[i][j], fah[i], fbl[jp][o], fbl[jp][o + 1]);
                    mma16816(acc[i][j], fal[i], fbh[jp][o], fbh[jp][o + 1]);
                }
        }
        __syncthreads();
    }

    // epilogue: add mask, store masked logits
    const int* ms = (const int*)(smem + QK_MASK);
#pragma unroll
    for (int j = 0; j < 4; j++) {
        int c0 = wn * 32 + j * 8 + 2 * tg;
        float t0 = (1.0f - (float)ms[c0]) * NEG_INF;
        float t1 = (1.0f - (float)ms[c0 + 1]) * NEG_INF;
#pragma unroll
        for (int i = 0; i < 2; i++) {
            int r0 = bm * 128 + wm * 32 + i * 16 + g;
            size_t base = ((size_t)bz * TQ + r0) * TK + bn * 128 + c0;
            *(float2*)(&S[base]) = make_float2(acc[i][j][0] + t0, acc[i][j][1] + t1);
            *(float2*)(&S[base + (size_t)8 * TK]) = make_float2(acc[i][j][2] + t0, acc[i][j][3] + t1);
        }
    }
}

// ------------------------------------------------------------ row softmax (in place)
__global__ __launch_bounds__(256) void softmax_kernel(float* __restrict__ W)
{
    const size_t row = blockIdx.x;
    float4* p = reinterpret_cast<float4*>(W + row * TK);
    const int tid = threadIdx.x;
    const int lane = tid & 31, warp = tid >> 5;
    __shared__ float red[8];

    float4 v0 = p[tid];
    float4 v1 = p[tid + 256];

    float mx = fmaxf(fmaxf(fmaxf(v0.x, v0.y), fmaxf(v0.z, v0.w)),
                     fmaxf(fmaxf(v1.x, v1.y), fmaxf(v1.z, v1.w)));
#pragma unroll
    for (int o = 16; o; o >>= 1) mx = fmaxf(mx, __shfl_xor_sync(0xffffffffu, mx, o));
    if (lane == 0) red[warp] = mx;
    __syncthreads();
    float bmax = red[0];
#pragma unroll
    for (int i = 1; i < 8; i++) bmax = fmaxf(bmax, red[i]);
    __syncthreads();

    v0.x = __expf(v0.x - bmax); v0.y = __expf(v0.y - bmax);
    v0.z = __expf(v0.z - bmax); v0.w = __expf(v0.w - bmax);
    v1.x = __expf(v1.x - bmax); v1.y = __expf(v1.y - bmax);
    v1.z = __expf(v1.z - bmax); v1.w = __expf(v1.w - bmax);

    float s = (v0.x + v0.y + v0.z + v0.w) + (v1.x + v1.y + v1.z + v1.w);
#pragma unroll
    for (int o = 16; o; o >>= 1) s += __shfl_xor_sync(0xffffffffu, s, o);
    if (lane == 0) red[warp] = s;
    __syncthreads();
    float bsum = red[0];
#pragma unroll
    for (int i = 1; i < 8; i++) bsum += red[i];

    const float inv = 1.0f / bsum;
    v0.x *= inv; v0.y *= inv; v0.z *= inv; v0.w *= inv;
    v1.x *= inv; v1.y *= inv; v1.z *= inv; v1.w *= inv;
    p[tid] = v0;
    p[tid + 256] = v1;
}

// ------------------------------------------------------------ P @ V (fp16 2-term)
// ctx = P@V with P split (hi+lo), V hi only: terms Ph*Vh + Pl*Vh.
// A = W (K-major, ldmatrix). V chunk stored [k][d], read via ldmatrix.trans.
__global__ __launch_bounds__(NT, 1) void pv_kernel(
    const float* __restrict__ W, const float* __restrict__ enc, float* __restrict__ ctx)
{
    extern __shared__ char smem[];
    const int tid = threadIdx.x, warp = tid >> 5, lane = tid & 31;
    const int g = lane >> 2, tg = lane & 3;
    const int r8 = lane & 7, sub = lane >> 3;
    const int wm = warp >> 2, wn = warp & 3;
    const int bz = blockIdx.z, bm = blockIdx.y, bn = blockIdx.x;

    const float* Ag = W + ((size_t)bz * TQ + bm * 128) * TK;
    const float* Eg = enc + (size_t)bz * TK * D + bn * 128;

    float acc[2][4][4];
#pragma unroll
    for (int i = 0; i < 2; i++)
#pragma unroll
        for (int j = 0; j < 4; j++)
#pragma unroll
            for (int t = 0; t < 4; t++) acc[i][j][t] = 0.f;

    const uint32_t sb = smem_u32(smem);

    // A: p -> row = p>>4, q = p&15 ; V: p -> krow = p>>5, dq = p&31
    float4 ra[4], rv[4];
#pragma unroll
    for (int i = 0; i < 4; i++) {
        int p = tid + NT * i;
        ra[i] = *(const float4*)(Ag + (size_t)(p >> 4) * TK + (p & 15) * 4);
        rv[i] = *(const float4*)(Eg + (size_t)(p >> 5) * D + (p & 31) * 4);
    }
    {
        char* Ah = smem;                 char* Al = Ah + PV_ATILE;
        char* Vh = Al + PV_ATILE;
#pragma unroll
        for (int i = 0; i < 4; i++) {
            int p = tid + NT * i, r = p >> 4, qq = p & 15;
            uint32_t off = r * (PA * 2) + qq * 8;
            uint2 hi, lo;
            split4(ra[i], hi, lo);
            *(uint2*)(Ah + off) = hi;  *(uint2*)(Al + off) = lo;
            uint32_t voff = (p >> 5) * (PB * 2) + (p & 31) * 8;
            *(uint2*)(Vh + voff) = hi4(rv[i]);
        }
#pragma unroll
        for (int i = 0; i < 4; i++) {
            int p = tid + NT * i;
            ra[i] = *(const float4*)(Ag + (size_t)(p >> 4) * TK + KC + (p & 15) * 4);
            rv[i] = *(const float4*)(Eg + (size_t)(KC + (p >> 5)) * D + (p & 31) * 4);
        }
    }
    __syncthreads();

    for (int k = 0; k < PV_CHUNKS; k++) {
        const int buf = k & 1;
        const uint32_t sAh = sb + buf * PV_STAGE;
        const uint32_t sAl = sAh + PV_ATILE;
        const uint32_t sVh = sAl + PV_ATILE;
        char* nAh = smem + (buf ^ 1) * PV_STAGE;
        char* nAl = nAh + PV_ATILE;
        char* nVh = nAl + PV_ATILE;

        const uint32_t aoff = (wm * 32 + r8 + (sub & 1) * 8) * (PA * 2) + ((sub >> 1) * 8) * 2;
        const uint32_t voff = (r8 + (sub & 1) * 8) * (PB * 2)
                            + (wn * 32 + (sub >> 1) * 8) * 2;

        uint32_t fah[2][4], fal[2][4], fbh[2][4];

#pragma unroll
        for (int kk = 0; kk < 4; kk++) {
#pragma unroll
            for (int i = 0; i < 2; i++) {
                ldsm4(fah[i], sAh + aoff + kk * 32 + i * 16 * (PA * 2));
                ldsm4(fal[i], sAl + aoff + kk * 32 + i * 16 * (PA * 2));
            }
#pragma unroll
            for (int jp = 0; jp < 2; jp++) {
                ldsm4t(fbh[jp], sVh + voff + kk * 16 * (PB * 2) + jp * 16 * 2);
            }
            if (kk == 0) {
                if (k + 1 < PV_CHUNKS) {
#pragma unroll
                    for (int i = 0; i < 4; i++) {
                        int p = tid + NT * i, r = p >> 4, qq = p & 15;
                        uint32_t off = r * (PA * 2) + qq * 8;
                        uint2 hi, lo;
                        split4(ra[i], hi, lo);
                        *(uint2*)(nAh + off) = hi;  *(uint2*)(nAl + off) = lo;
                        uint32_t voff2 = (p >> 5) * (PB * 2) + (p & 31) * 8;
                        *(uint2*)(nVh + voff2) = hi4(rv[i]);
                    }
                }
            } else if (kk == 2) {
                if (k + 2 < PV_CHUNKS) {
                    const int ko = (k + 2) * KC;
#pragma unroll
                    for (int i = 0; i < 4; i++) {
                        int p = tid + NT * i;
                        ra[i] = *(const float4*)(Ag + (size_t)(p >> 4) * TK + ko + (p & 15) * 4);
                        rv[i] = *(const float4*)(Eg + (size_t)(ko + (p >> 5)) * D + (p & 31) * 4);
                    }
                }
            }
#pragma unroll
            for (int i = 0; i < 2; i++)
#pragma unroll
                for (int j = 0; j < 4; j++) {
                    int jp = j >> 1, o = (j & 1) * 2;
                    mma16816(acc[i][j], fah[i], fbh[jp][o], fbh[jp][o + 1]);
                    mma16816(acc[i][j], fal[i], fbh[jp][o], fbh[jp][o + 1]);
                }
        }
        __syncthreads();
    }

#pragma unroll
    for (int j = 0; j < 4; j++) {
        int c0 = wn * 32 + j * 8 + 2 * tg;
#pragma unroll
        for (int i = 0; i < 2; i++) {
            int r0 = bm * 128 + wm * 32 + i * 16 + g;
            size_t base = ((size_t)bz * TQ + r0) * D + bn * 128 + c0;
            *(float2*)(&ctx[base]) = make_float2(acc[i][j][0], acc[i][j][1]);
            *(float2*)(&ctx[base + (size_t)8 * D]) = make_float2(acc[i][j][2], acc[i][j][3]);
        }
    }
}

// ---------------------------------------------------------------- launcher
extern "C" void kernel_launch(void* const* d_in, const int* in_sizes, int n_in,
                              void* d_out, int out_size)
{
    const float* dec  = (const float*)d_in[0];   // [B, TQ, D]
    const float* enc  = (const float*)d_in[1];   // [B, TK, D]
    const int*   mask = (const int*)d_in[2];     // [B, TK]
    float* out = (float*)d_out;

    float* ctx = out;                              // [B, TQ, D]
    float* Wgt = out + (size_t)B * TQ * D;         // [B, TQ, TK]

    cudaFuncSetAttribute(qk_kernel, cudaFuncAttributeMaxDynamicSharedMemorySize, QK_SMEM);
    cudaFuncSetAttribute(pv_kernel, cudaFuncAttributeMaxDynamicSharedMemorySize, PV_SMEM);

    dim3 g1(TK / 128, TQ / 128, B);
    qk_kernel<<<g1, NT, QK_SMEM>>>(dec, enc, mask, Wgt);

    softmax_kernel<<<B * TQ, 256>>>(Wgt);

    dim3 g3(D / 128, TQ / 128, B);
    pv_kernel<<<g3, NT, PV_SMEM>>>(Wgt, enc, ctx);
}